// round 7
// baseline (speedup 1.0000x reference)
#include <cuda_runtime.h>
#include <cuda.h>
#include <cstdint>

// DotProductAttention (B=4, C=80, 512x512 fp32). Pure HBM stream, 369MB.
// R7: single 2D TMA tensor-tile load per 80KB stage (box 256x80 over the
// input viewed as (HW, B*C)) replaces 80 hand-issued cp.async.bulk copies --
// kills producer-side ALU/issue overhead. 2-stage ring, FMA-only exp2 softmax.

#define NK_   8
#define NV_   8
#define NCH_  80
#define HW_   262144                 // 512*512
#define PIX_  256                    // pixels per tile
#define CHUNKS_PER_B (HW_ / PIX_)    // 1024
#define TOTAL_CHUNKS (CHUNKS_PER_B * 4)     // 4096
#define TILE_BYTES (NCH_ * PIX_ * 4)        // 81920
#define SMEM_BARS 128
#define SMEM_TOTAL (SMEM_BARS + 2 * TILE_BYTES)   // 163968
#define GRID_    148
#define THREADS_ 256

__device__ __forceinline__ uint32_t smem_u32(const void* p) {
    return (uint32_t)__cvta_generic_to_shared(p);
}
__device__ __forceinline__ void mbar_init(uint32_t a, uint32_t cnt) {
    asm volatile("mbarrier.init.shared.b64 [%0], %1;" :: "r"(a), "r"(cnt) : "memory");
}
__device__ __forceinline__ void mbar_expect_tx(uint32_t a, uint32_t bytes) {
    asm volatile("mbarrier.arrive.expect_tx.shared.b64 _, [%0], %1;"
                 :: "r"(a), "r"(bytes) : "memory");
}
__device__ __forceinline__ void mbar_wait(uint32_t a, uint32_t parity) {
    asm volatile(
        "{\n\t.reg .pred P;\n\t"
        "WAIT_%=:\n\t"
        "mbarrier.try_wait.parity.acquire.cta.shared::cta.b64 P, [%0], %1, 0x989680;\n\t"
        "@P bra.uni DONE_%=;\n\t"
        "bra.uni WAIT_%=;\n\t"
        "DONE_%=:\n\t}"
        :: "r"(a), "r"(parity) : "memory");
}
__device__ __forceinline__ void tma_load_2d_hint(
    uint32_t dst, const CUtensorMap* map, int x, int y,
    uint32_t mbar, uint64_t pol)
{
    asm volatile(
        "cp.async.bulk.tensor.2d.shared::cluster.global.tile"
        ".mbarrier::complete_tx::bytes.L2::cache_hint "
        "[%0], [%1, {%2, %3}], [%4], %5;"
        :: "r"(dst), "l"(map), "r"(x), "r"(y), "r"(mbar), "l"(pol) : "memory");
}

// exp2 of t (t <= 0, clamped >= -80), FMA/ALU only. Rel err ~2e-6.
__device__ __forceinline__ float fast_exp2(float t) {
    t = fmaxf(t, -80.0f);
    float tf = t + 12582912.0f;                 // 1.5 * 2^23 : round-to-nearest
    int   n  = __float_as_int(tf);
    float f  = t - (tf - 12582912.0f);          // f in [-0.5, 0.5]
    float p = 1.33335581e-3f;
    p = fmaf(p, f, 9.61812911e-3f);
    p = fmaf(p, f, 5.55041087e-2f);
    p = fmaf(p, f, 2.40226507e-1f);
    p = fmaf(p, f, 6.93147182e-1f);
    p = fmaf(p, f, 1.0f);
    return __int_as_float(__float_as_int(p) + (n << 23));
}

__global__ void __launch_bounds__(THREADS_, 1)
dpa_kernel(const __grid_constant__ CUtensorMap tmap, float* __restrict__ out)
{
    extern __shared__ char smem[];
    const uint32_t sbase = smem_u32(smem);
    const int tid = threadIdx.x;

    const uint32_t full0 = sbase;               // two mbarriers: +0, +8
    const uint32_t tile_s0 = sbase + SMEM_BARS;

    uint64_t pol;
    asm("createpolicy.fractional.L2::evict_first.b64 %0, 1.0;" : "=l"(pol));

    if (tid == 0) {
        mbar_init(full0, 1);
        mbar_init(full0 + 8, 1);
        asm volatile("fence.proxy.async.shared::cta;" ::: "memory");
    }
    __syncthreads();

    auto issue_tile = [&](int s, int chunk) {
        const int b  = chunk >> 10;             // / CHUNKS_PER_B
        const int cb = chunk & (CHUNKS_PER_B - 1);
        const uint32_t mb = full0 + s * 8;
        mbar_expect_tx(mb, TILE_BYTES);
        tma_load_2d_hint(tile_s0 + s * TILE_BYTES, &tmap,
                         cb * PIX_, b * NCH_, mb, pol);
    };

    // prologue: fill both stages
    if (tid == 0) {
        if (blockIdx.x < TOTAL_CHUNKS)          issue_tile(0, blockIdx.x);
        if (blockIdx.x + GRID_ < TOTAL_CHUNKS)  issue_tile(1, blockIdx.x + GRID_);
    }

    const float C = 0.51006952f;                // log2(e)/sqrt(8)

    for (int j = 0, chunk = blockIdx.x; chunk < TOTAL_CHUNKS;
         j++, chunk += GRID_) {
        const int s = j & 1;
        const uint32_t parity = (j >> 1) & 1;
        mbar_wait(full0 + s * 8, parity);

        const float* tile = (const float*)(smem + SMEM_BARS + s * TILE_BYTES);

        // ---- per-pixel compute (thread t = pixel t of the tile) ----
        float q[NK_];
#pragma unroll
        for (int i = 0; i < NK_; i++)
            q[i] = tile[i * PIX_ + tid];

        float qk[NV_];
#pragma unroll
        for (int v = 0; v < NV_; v++) qk[v] = 0.0f;
#pragma unroll
        for (int kk = 0; kk < NK_; kk++) {
#pragma unroll
            for (int v = 0; v < NV_; v++)
                qk[v] = fmaf(q[kk], tile[(NK_ + kk * NV_ + v) * PIX_ + tid], qk[v]);
        }

        float m = qk[0];
#pragma unroll
        for (int v = 1; v < NV_; v++) m = fmaxf(m, qk[v]);
        const float mC = m * C;
        float ssum = 0.0f;
#pragma unroll
        for (int v = 0; v < NV_; v++) {
            qk[v] = fast_exp2(fmaf(qk[v], C, -mC));   // 2^(C*(qk-m))
            ssum += qk[v];
        }
        const float inv = __frcp_rn(ssum);

        const int b  = chunk >> 10;
        const int cb = chunk & (CHUNKS_PER_B - 1);
        float* obase = out + (size_t)b * NV_ * HW_ + cb * PIX_ + tid;
#pragma unroll
        for (int v = 0; v < NV_; v++) {
            float vv = tile[(NK_ + NK_ * NV_ + v) * PIX_ + tid];
            __stcs(obase + v * HW_, qk[v] * inv * vv);
        }

        // stage s fully consumed -> refill
        __syncthreads();
        const int cn = chunk + 2 * GRID_;
        if (tid == 0 && cn < TOTAL_CHUNKS)
            issue_tile(s, cn);
    }
}

// -- host side ---------------------------------------------------------------

typedef CUresult (*PFN_encodeTiled)(
    CUtensorMap*, CUtensorMapDataType, cuuint32_t, void*,
    const cuuint64_t*, const cuuint64_t*, const cuuint32_t*, const cuuint32_t*,
    CUtensorMapInterleave, CUtensorMapSwizzle, CUtensorMapL2promotion,
    CUtensorMapFloatOOBfill);

extern "C" void kernel_launch(void* const* d_in, const int* in_sizes, int n_in,
                              void* d_out, int out_size)
{
    float* out = (float*)d_out;

    static PFN_encodeTiled encode_fn = nullptr;
    static int configured = 0;
    if (!configured) {
        cudaFuncSetAttribute(dpa_kernel,
                             cudaFuncAttributeMaxDynamicSharedMemorySize,
                             SMEM_TOTAL);
        void* fp = nullptr;
        cudaDriverEntryPointQueryResult qres;
        cudaGetDriverEntryPoint("cuTensorMapEncodeTiled", &fp,
                                cudaEnableDefault, &qres);
        encode_fn = (PFN_encodeTiled)fp;
        configured = 1;
    }

    // input viewed as 2D: dim0 = HW (contiguous), dim1 = B*C (stride HW*4B)
    CUtensorMap tmap;
    {
        cuuint64_t dims[2]    = {(cuuint64_t)HW_, (cuuint64_t)(4 * NCH_)};
        cuuint64_t strides[1] = {(cuuint64_t)HW_ * 4};
        cuuint32_t box[2]     = {PIX_, NCH_};
        cuuint32_t estr[2]    = {1, 1};
        encode_fn(&tmap, CU_TENSOR_MAP_DATA_TYPE_FLOAT32, 2, d_in[0],
                  dims, strides, box, estr,
                  CU_TENSOR_MAP_INTERLEAVE_NONE, CU_TENSOR_MAP_SWIZZLE_NONE,
                  CU_TENSOR_MAP_L2_PROMOTION_L2_128B,
                  CU_TENSOR_MAP_FLOAT_OOB_FILL_NONE);
    }

    dpa_kernel<<<GRID_, THREADS_, SMEM_TOTAL>>>(tmap, out);
}